// round 1
// baseline (speedup 1.0000x reference)
#include <cuda_runtime.h>

#define BB 8
#define NN 2048
#define DD 128
#define SHIFT 20.0f

// ---------------- scratch (static device globals; no allocation) ----------------
__device__ float g_H[BB * NN * DD];                 // 8 MB
__device__ float g_G[BB * NN * DD];                 // 8 MB
__device__ float g_P[(size_t)BB * NN * NN];         // 134 MB
__device__ float g_colsum[BB * NN];                 // colsum, then inverted in-place

// ---------------- K1: C[r,c] = X[r,128] @ W[128,128] (+bias) ----------------
// mode 0: X = x (input), C = g_H, with bias
// mode 1: X = g_H,       C = g_G, no bias
__global__ __launch_bounds__(256) void gemm_k(const float* __restrict__ Xin,
                                              const float* __restrict__ W,
                                              const float* __restrict__ bias,
                                              int mode)
{
    __shared__ float Xs[16][68];
    __shared__ float Ws[16][128];
    const float* X = mode ? g_H : Xin;
    float* C = mode ? g_G : g_H;

    int tid = threadIdx.x;
    int tx = tid & 15, ty = tid >> 4;
    int r0 = blockIdx.x * 64;

    float acc[4][8];
#pragma unroll
    for (int i = 0; i < 4; i++)
#pragma unroll
        for (int j = 0; j < 8; j++) acc[i][j] = 0.f;

    for (int k0 = 0; k0 < 128; k0 += 16) {
        {   // X tile: 64 rows x 16 k  (256 float4, 1/thread), transposed store
            int row = tid >> 2, c4 = tid & 3;
            float4 v = *(const float4*)(X + (size_t)(r0 + row) * DD + k0 + c4 * 4);
            Xs[c4 * 4 + 0][row] = v.x; Xs[c4 * 4 + 1][row] = v.y;
            Xs[c4 * 4 + 2][row] = v.z; Xs[c4 * 4 + 3][row] = v.w;
        }
#pragma unroll
        for (int it = 0; it < 2; it++) {   // W tile: 16 x 128 (512 float4, 2/thread)
            int f = tid + it * 256; int kk = f >> 5, c4 = f & 31;
            *(float4*)(&Ws[kk][c4 * 4]) = *(const float4*)(W + (size_t)(k0 + kk) * DD + c4 * 4);
        }
        __syncthreads();
#pragma unroll
        for (int kk = 0; kk < 16; kk++) {
            float a[4], bv[8];
#pragma unroll
            for (int i = 0; i < 4; i++) a[i] = Xs[kk][ty * 4 + i];
#pragma unroll
            for (int j = 0; j < 8; j++) bv[j] = Ws[kk][tx + 16 * j];
#pragma unroll
            for (int i = 0; i < 4; i++)
#pragma unroll
                for (int j = 0; j < 8; j++) acc[i][j] += a[i] * bv[j];
        }
        __syncthreads();
    }

    float bj[8];
#pragma unroll
    for (int j = 0; j < 8; j++) bj[j] = bias ? bias[tx + 16 * j] : 0.f;
#pragma unroll
    for (int i = 0; i < 4; i++) {
        int r = r0 + ty * 4 + i;
#pragma unroll
        for (int j = 0; j < 8; j++) {
            int c = tx + 16 * j;
            C[(size_t)r * DD + c] = acc[i][j] + bj[j];
        }
    }
}

// ---------------- zero colsum ----------------
__global__ void zero_colsum_k()
{
    int i = blockIdx.x * 256 + threadIdx.x;
    if (i < BB * NN) g_colsum[i] = 0.f;
}

// ---------------- K2: scores + exp + mask + colsum + write P ----------------
// e[n,m] = H_n.G_m + G_n.H_m  (K=256 GEMM);  p = adj * exp(e - SHIFT)
// block: (m-tile of 128 cols) x (half of n range); tile 128x128, thread 8x8
__global__ __launch_bounds__(256, 2) void score_k(const float* __restrict__ adj)
{
    __shared__ float As[16][132];
    __shared__ float Bs[16][132];

    int tid = threadIdx.x;
    int tx = tid & 15, ty = tid >> 4;
    int b = blockIdx.z;
    int m0 = blockIdx.x * 128;
    int nbase = blockIdx.y * (NN / 2);

    const float* Hb = g_H + (size_t)b * NN * DD;
    const float* Gb = g_G + (size_t)b * NN * DD;

    float csum[8];
#pragma unroll
    for (int j = 0; j < 8; j++) csum[j] = 0.f;

    for (int nt = 0; nt < NN / 2; nt += 128) {
        int n0 = nbase + nt;
        float acc[8][8];
#pragma unroll
        for (int i = 0; i < 8; i++)
#pragma unroll
            for (int j = 0; j < 8; j++) acc[i][j] = 0.f;

#pragma unroll
        for (int half = 0; half < 2; half++) {
            const float* Ag = half ? Gb : Hb;   // rows n
            const float* Bg = half ? Hb : Gb;   // rows m
            for (int k0 = 0; k0 < 128; k0 += 16) {
#pragma unroll
                for (int it = 0; it < 2; it++) {   // 128 rows x 4 float4, 2/thread each side
                    int f = tid + it * 256; int row = f >> 2, c4 = f & 3;
                    float4 v = *(const float4*)(Ag + (size_t)(n0 + row) * DD + k0 + c4 * 4);
                    As[c4 * 4 + 0][row] = v.x; As[c4 * 4 + 1][row] = v.y;
                    As[c4 * 4 + 2][row] = v.z; As[c4 * 4 + 3][row] = v.w;
                    float4 w = *(const float4*)(Bg + (size_t)(m0 + row) * DD + k0 + c4 * 4);
                    Bs[c4 * 4 + 0][row] = w.x; Bs[c4 * 4 + 1][row] = w.y;
                    Bs[c4 * 4 + 2][row] = w.z; Bs[c4 * 4 + 3][row] = w.w;
                }
                __syncthreads();
#pragma unroll
                for (int kk = 0; kk < 16; kk++) {
                    float a[8], bv[8];
#pragma unroll
                    for (int i = 0; i < 8; i++) a[i] = As[kk][ty * 8 + i];
#pragma unroll
                    for (int j = 0; j < 8; j++) bv[j] = Bs[kk][tx + 16 * j];
#pragma unroll
                    for (int i = 0; i < 8; i++)
#pragma unroll
                        for (int j = 0; j < 8; j++) acc[i][j] += a[i] * bv[j];
                }
                __syncthreads();
            }
        }

        // epilogue: mask, exp, write P, accumulate column sums
        const float* adjb = adj + ((size_t)b * NN + n0) * NN + m0;
        float* Pb = g_P + ((size_t)b * NN + n0) * NN + m0;
#pragma unroll
        for (int i = 0; i < 8; i++) {
            int r = ty * 8 + i;
#pragma unroll
            for (int j = 0; j < 8; j++) {
                int c = tx + 16 * j;
                float a = adjb[(size_t)r * NN + c];
                float p = a * __expf(acc[i][j] - SHIFT);
                Pb[(size_t)r * NN + c] = p;
                csum[j] += p;
            }
        }
    }

    // cross-ty reduce of column partials, then one atomic per column
    __syncthreads();
    float* red = &As[0][0];   // 2112 floats available, need 2048
#pragma unroll
    for (int j = 0; j < 8; j++) red[ty * 128 + tx + 16 * j] = csum[j];
    __syncthreads();
    if (tid < 128) {
        float s = 0.f;
#pragma unroll
        for (int t = 0; t < 16; t++) s += red[t * 128 + tid];
        atomicAdd(&g_colsum[b * NN + m0 + tid], s);
    }
}

// ---------------- invert colsum in place ----------------
__global__ void inv_colsum_k()
{
    int i = blockIdx.x * 256 + threadIdx.x;
    if (i < BB * NN) {
        float s = g_colsum[i];
        g_colsum[i] = (s > 0.f) ? 1.f / s : 0.f;
    }
}

// ---------------- K3: h' = P @ (H * inv), relu, gate, final mix ----------------
// block: 64 n-rows x 128 d-cols (full D), thread tile 4x8
__global__ __launch_bounds__(256, 2) void out_k(const float* __restrict__ x,
                                                const float* __restrict__ gate_w,
                                                const float* __restrict__ gate_b,
                                                float* __restrict__ out)
{
    __shared__ float Ps[16][68];     // [kk][n-row]
    __shared__ float Hs[16][132];    // [kk][d], pre-scaled by inv colsum
    __shared__ float gws[256];
    __shared__ float sred[64][17];
    __shared__ float coef[64];

    int tid = threadIdx.x;
    int tx = tid & 15, ty = tid >> 4;
    int b = blockIdx.y;
    int n0 = blockIdx.x * 64;

    gws[tid] = gate_w[tid];

    const float* Pb = g_P + ((size_t)b * NN + n0) * NN;
    const float* Hb = g_H + (size_t)b * NN * DD;
    const float* cs = g_colsum + b * NN;   // holds inverse after inv_colsum_k

    float acc[4][8];
#pragma unroll
    for (int i = 0; i < 4; i++)
#pragma unroll
        for (int j = 0; j < 8; j++) acc[i][j] = 0.f;

    for (int k0 = 0; k0 < NN; k0 += 16) {
        {   // P tile: 64 rows x 16 m (256 float4, 1/thread)
            int row = tid >> 2, c4 = tid & 3;
            float4 v = *(const float4*)(Pb + (size_t)row * NN + k0 + c4 * 4);
            Ps[c4 * 4 + 0][row] = v.x; Ps[c4 * 4 + 1][row] = v.y;
            Ps[c4 * 4 + 2][row] = v.z; Ps[c4 * 4 + 3][row] = v.w;
        }
#pragma unroll
        for (int it = 0; it < 2; it++) {   // H tile: 16 m-rows x 128 d, scaled
            int f = tid + it * 256; int kk = f >> 5, c4 = f & 31;
            float inv = cs[k0 + kk];
            float4 v = *(const float4*)(Hb + (size_t)(k0 + kk) * DD + c4 * 4);
            Hs[kk][c4 * 4 + 0] = v.x * inv; Hs[kk][c4 * 4 + 1] = v.y * inv;
            Hs[kk][c4 * 4 + 2] = v.z * inv; Hs[kk][c4 * 4 + 3] = v.w * inv;
        }
        __syncthreads();
#pragma unroll
        for (int kk = 0; kk < 16; kk++) {
            float a[4], bv[8];
#pragma unroll
            for (int i = 0; i < 4; i++) a[i] = Ps[kk][ty * 4 + i];
#pragma unroll
            for (int j = 0; j < 8; j++) bv[j] = Hs[kk][tx + 16 * j];
#pragma unroll
            for (int i = 0; i < 4; i++)
#pragma unroll
                for (int j = 0; j < 8; j++) acc[i][j] += a[i] * bv[j];
        }
        __syncthreads();
    }

    // relu + per-thread gate partial (x part + h' part)
#pragma unroll
    for (int i = 0; i < 4; i++) {
        int n = n0 + ty * 4 + i;
        float p = 0.f;
#pragma unroll
        for (int j = 0; j < 8; j++) {
            int d = tx + 16 * j;
            float hp = fmaxf(acc[i][j], 0.f);
            acc[i][j] = hp;
            float xv = x[((size_t)b * NN + n) * DD + d];
            p += xv * gws[d] + hp * gws[128 + d];
        }
        sred[ty * 4 + i][tx] = p;
    }
    __syncthreads();
    if (tid < 64) {
        float s = 0.f;
#pragma unroll
        for (int t = 0; t < 16; t++) s += sred[tid][t];
        s += gate_b[0];
        coef[tid] = 1.f / (1.f + __expf(-s));
    }
    __syncthreads();

#pragma unroll
    for (int i = 0; i < 4; i++) {
        int n = n0 + ty * 4 + i;
        float c = coef[ty * 4 + i];
#pragma unroll
        for (int j = 0; j < 8; j++) {
            int d = tx + 16 * j;
            float xv = x[((size_t)b * NN + n) * DD + d];
            out[((size_t)b * NN + n) * DD + d] = c * xv + (1.f - c) * acc[i][j];
        }
    }
}

// ---------------- launch ----------------
extern "C" void kernel_launch(void* const* d_in, const int* in_sizes, int n_in,
                              void* d_out, int out_size)
{
    const float* x      = (const float*)d_in[0];
    const float* adj    = (const float*)d_in[1];
    const float* W_w    = (const float*)d_in[2];
    const float* W_b    = (const float*)d_in[3];
    const float* A_w    = (const float*)d_in[4];
    const float* gate_w = (const float*)d_in[5];
    const float* gate_b = (const float*)d_in[6];
    float* out = (float*)d_out;

    gemm_k<<<BB * NN / 64, 256>>>(x, W_w, W_b, 0);          // g_H = xW + b
    gemm_k<<<BB * NN / 64, 256>>>(nullptr, A_w, nullptr, 1); // g_G = g_H A
    zero_colsum_k<<<BB * NN / 256, 256>>>();
    score_k<<<dim3(NN / 128, 2, BB), 256>>>(adj);            // P, colsum
    inv_colsum_k<<<BB * NN / 256, 256>>>();
    out_k<<<dim3(NN / 64, BB), 256>>>(x, gate_w, gate_b, out);
}

// round 4
// speedup vs baseline: 1.5913x; 1.5913x over previous
#include <cuda_runtime.h>
#include <cuda_bf16.h>
#include <cstdint>

#define BB 8
#define NN 2048
#define DD 128
#define SHIFT 20.0f

// ---------------- scratch (static device globals; no allocation) ----------------
__device__ float g_H[BB * NN * DD];                 // 8 MB
__device__ float g_G[BB * NN * DD];                 // 8 MB
__device__ float g_P[(size_t)BB * NN * NN];         // 134 MB
__device__ float g_colsum[BB * NN];
// split bf16 of S = [H | G] per row (K=256)
__device__ __nv_bfloat16 g_Shi[(size_t)BB * NN * 256];   // 8 MB
__device__ __nv_bfloat16 g_Slo[(size_t)BB * NN * 256];   // 8 MB

// ================= warp MMA helpers (plain PTX, sm_80+) =================
__device__ __forceinline__ uint32_t smem_u32(const void* p) {
    uint32_t a;
    asm("{ .reg .u64 t; cvta.to.shared.u64 t, %1; cvt.u32.u64 %0, t; }" : "=r"(a) : "l"(p));
    return a;
}
__device__ __forceinline__ void ldsm_x4(uint32_t& r0, uint32_t& r1, uint32_t& r2, uint32_t& r3,
                                        uint32_t addr) {
    asm volatile("ldmatrix.sync.aligned.m8n8.x4.shared.b16 {%0,%1,%2,%3}, [%4];"
                 : "=r"(r0), "=r"(r1), "=r"(r2), "=r"(r3) : "r"(addr));
}
__device__ __forceinline__ void mma16816(float* d, const uint32_t* a, uint32_t b0, uint32_t b1) {
    asm volatile(
        "mma.sync.aligned.m16n8k16.row.col.f32.bf16.bf16.f32 "
        "{%0,%1,%2,%3}, {%4,%5,%6,%7}, {%8,%9}, {%0,%1,%2,%3};"
        : "+f"(d[0]), "+f"(d[1]), "+f"(d[2]), "+f"(d[3])
        : "r"(a[0]), "r"(a[1]), "r"(a[2]), "r"(a[3]), "r"(b0), "r"(b1));
}

// ---------------- K1: C[r,c] = X[r,128] @ W[128,128] (+bias) ----------------
__global__ __launch_bounds__(256) void gemm_k(const float* __restrict__ Xin,
                                              const float* __restrict__ W,
                                              const float* __restrict__ bias,
                                              int mode)
{
    __shared__ float Xs[16][68];
    __shared__ float Ws[16][128];
    const float* X = mode ? g_H : Xin;
    float* C = mode ? g_G : g_H;

    int tid = threadIdx.x;
    int tx = tid & 15, ty = tid >> 4;
    int r0 = blockIdx.x * 64;

    float acc[4][8];
#pragma unroll
    for (int i = 0; i < 4; i++)
#pragma unroll
        for (int j = 0; j < 8; j++) acc[i][j] = 0.f;

    for (int k0 = 0; k0 < 128; k0 += 16) {
        {
            int row = tid >> 2, c4 = tid & 3;
            float4 v = *(const float4*)(X + (size_t)(r0 + row) * DD + k0 + c4 * 4);
            Xs[c4 * 4 + 0][row] = v.x; Xs[c4 * 4 + 1][row] = v.y;
            Xs[c4 * 4 + 2][row] = v.z; Xs[c4 * 4 + 3][row] = v.w;
        }
#pragma unroll
        for (int it = 0; it < 2; it++) {
            int f = tid + it * 256; int kk = f >> 5, c4 = f & 31;
            *(float4*)(&Ws[kk][c4 * 4]) = *(const float4*)(W + (size_t)(k0 + kk) * DD + c4 * 4);
        }
        __syncthreads();
#pragma unroll
        for (int kk = 0; kk < 16; kk++) {
            float a[4], bv[8];
#pragma unroll
            for (int i = 0; i < 4; i++) a[i] = Xs[kk][ty * 4 + i];
#pragma unroll
            for (int j = 0; j < 8; j++) bv[j] = Ws[kk][tx + 16 * j];
#pragma unroll
            for (int i = 0; i < 4; i++)
#pragma unroll
                for (int j = 0; j < 8; j++) acc[i][j] += a[i] * bv[j];
        }
        __syncthreads();
    }

    float bj[8];
#pragma unroll
    for (int j = 0; j < 8; j++) bj[j] = bias ? bias[tx + 16 * j] : 0.f;
#pragma unroll
    for (int i = 0; i < 4; i++) {
        int r = r0 + ty * 4 + i;
#pragma unroll
        for (int j = 0; j < 8; j++) {
            int c = tx + 16 * j;
            C[(size_t)r * DD + c] = acc[i][j] + bj[j];
        }
    }
}

// ---------------- split H,G into bf16 hi/lo concatenated rows S=[H|G] ----------------
__global__ __launch_bounds__(128) void split_k()
{
    int row = blockIdx.x;
    int t = threadIdx.x;
    float h = g_H[(size_t)row * DD + t];
    float g = g_G[(size_t)row * DD + t];
    __nv_bfloat16 hh = __float2bfloat16(h);
    __nv_bfloat16 gh = __float2bfloat16(g);
    size_t base = (size_t)row * 256;
    g_Shi[base + t]       = hh;
    g_Slo[base + t]       = __float2bfloat16(h - __bfloat162float(hh));
    g_Shi[base + 128 + t] = gh;
    g_Slo[base + 128 + t] = __float2bfloat16(g - __bfloat162float(gh));
}

// ---------------- zero colsum ----------------
__global__ void zero_colsum_k()
{
    int i = blockIdx.x * 256 + threadIdx.x;
    if (i < BB * NN) g_colsum[i] = 0.f;
}

// ---------------- K2: score kernel via mma.sync bf16 (split fp32) ----------------
// D[n][m] tile 128x128 per CTA. e = S_n(chunk c) . S_m(chunk c+128 mod 256)
// passes: (Nhi,Mhi), (Nlo,Mhi), (Nhi,Mlo)
#define KC 32
#define LDS_STRIDE 40   // bf16 elems per row (pad 8): conflict-free ldmatrix, 16B-aligned rows

__global__ __launch_bounds__(256, 2) void score_k(const float* __restrict__ adj)
{
    __shared__ __nv_bfloat16 sNhi[128 * LDS_STRIDE];
    __shared__ __nv_bfloat16 sNlo[128 * LDS_STRIDE];
    __shared__ __nv_bfloat16 sMhi[128 * LDS_STRIDE];
    __shared__ __nv_bfloat16 sMlo[128 * LDS_STRIDE];

    int tid = threadIdx.x;
    int wid = tid >> 5, lane = tid & 31;
    int gid = lane >> 2, tig = lane & 3;

    int m0 = blockIdx.x * 128;
    int n0 = blockIdx.y * 128;
    int b  = blockIdx.z;

    int mw = (wid >> 2) * 64;   // warp m offset (2 warps)
    int nw = (wid & 3) * 32;    // warp n offset (4 warps)

    uint32_t aNhi = smem_u32(sNhi), aNlo = smem_u32(sNlo);
    uint32_t aMhi = smem_u32(sMhi), aMlo = smem_u32(sMlo);

    float acc[2][8][4];
#pragma unroll
    for (int i = 0; i < 2; i++)
#pragma unroll
        for (int j = 0; j < 8; j++)
#pragma unroll
            for (int k = 0; k < 4; k++) acc[i][j][k] = 0.f;

    // ldmatrix lane->address offsets (in bf16 elems)
    int aRow = lane & 15,                       aKof = (lane >> 4) << 3;   // A (n side)
    int bRow = (lane & 7) + ((lane >> 4) << 3), bKof = ((lane >> 3) & 1) << 3; // B (m side)

    for (int c = 0; c < 8; ++c) {
        size_t baseN = ((size_t)b * NN + n0) * 256 + (size_t)(c * KC);
        size_t baseM = ((size_t)b * NN + m0) * 256 + (size_t)(((c + 4) & 7) * KC);
        __syncthreads();   // previous chunk's ldmatrix done before overwrite
#pragma unroll
        for (int i = 0; i < 2; i++) {
            int f = tid + 256 * i;          // 0..511
            int row = f >> 2, seg = f & 3;  // 4x16B per row
            size_t gn = baseN + (size_t)row * 256 + seg * 8;
            size_t gm = baseM + (size_t)row * 256 + seg * 8;
            uint4 vNh = *(const uint4*)(g_Shi + gn);
            uint4 vNl = *(const uint4*)(g_Slo + gn);
            uint4 vMh = *(const uint4*)(g_Shi + gm);
            uint4 vMl = *(const uint4*)(g_Slo + gm);
            int so = row * LDS_STRIDE + seg * 8;
            *(uint4*)(sNhi + so) = vNh;
            *(uint4*)(sNlo + so) = vNl;
            *(uint4*)(sMhi + so) = vMh;
            *(uint4*)(sMlo + so) = vMl;
        }
        __syncthreads();

#pragma unroll
        for (int pass = 0; pass < 3; pass++) {
            uint32_t At = (pass == 1) ? aNlo : aNhi;
            uint32_t Bt = (pass == 2) ? aMlo : aMhi;
#pragma unroll
            for (int ks = 0; ks < 2; ks++) {
                int k0 = ks * 16;
                uint32_t afr[2][4];
#pragma unroll
                for (int nf = 0; nf < 2; nf++) {
                    uint32_t ad = At + (uint32_t)(((nw + nf * 16 + aRow) * LDS_STRIDE + k0 + aKof) * 2);
                    ldsm_x4(afr[nf][0], afr[nf][1], afr[nf][2], afr[nf][3], ad);
                }
                uint32_t bfr[4][4];
#pragma unroll
                for (int bi = 0; bi < 4; bi++) {
                    uint32_t ad = Bt + (uint32_t)(((mw + bi * 16 + bRow) * LDS_STRIDE + k0 + bKof) * 2);
                    ldsm_x4(bfr[bi][0], bfr[bi][1], bfr[bi][2], bfr[bi][3], ad);
                }
#pragma unroll
                for (int nf = 0; nf < 2; nf++)
#pragma unroll
                    for (int mf = 0; mf < 8; mf++) {
                        uint32_t b0 = bfr[mf >> 1][(mf & 1) ? 2 : 0];
                        uint32_t b1 = bfr[mf >> 1][(mf & 1) ? 3 : 1];
                        mma16816(acc[nf][mf], afr[nf], b0, b1);
                    }
            }
        }
    }

    // ---------------- epilogue: mask, exp, store P, colsum ----------------
    float cs0[8], cs1[8];
#pragma unroll
    for (int mf = 0; mf < 8; mf++) { cs0[mf] = 0.f; cs1[mf] = 0.f; }

#pragma unroll
    for (int nf = 0; nf < 2; nf++) {
#pragma unroll
        for (int half = 0; half < 2; half++) {
            int n = n0 + nw + nf * 16 + gid + half * 8;
            const float2* arow = (const float2*)(adj + ((size_t)b * NN + n) * NN + m0);
            float2* prow = (float2*)(g_P + ((size_t)b * NN + n) * NN + m0);
#pragma unroll
            for (int mf = 0; mf < 8; mf++) {
                int moff2 = (mw + mf * 8 + tig * 2) >> 1;   // float2 index
                float2 a2 = __ldg(arow + moff2);
                float c0 = acc[nf][mf][half * 2 + 0];
                float c1 = acc[nf][mf][half * 2 + 1];
                float p0 = a2.x * __expf(c0 - SHIFT);
                float p1 = a2.y * __expf(c1 - SHIFT);
                prow[moff2] = make_float2(p0, p1);
                cs0[mf] += p0;
                cs1[mf] += p1;
            }
        }
    }
    // reduce over gid lanes (xor 4,8,16), then tig lanes 0..3 do atomics
#pragma unroll
    for (int mf = 0; mf < 8; mf++) {
#pragma unroll
        for (int d = 4; d < 32; d <<= 1) {
            cs0[mf] += __shfl_xor_sync(0xFFFFFFFF, cs0[mf], d);
            cs1[mf] += __shfl_xor_sync(0xFFFFFFFF, cs1[mf], d);
        }
        if (lane < 4) {
            int m = m0 + mw + mf * 8 + lane * 2;
            atomicAdd(&g_colsum[b * NN + m],     cs0[mf]);
            atomicAdd(&g_colsum[b * NN + m + 1], cs1[mf]);
        }
    }
}

// ---------------- invert colsum in place ----------------
__global__ void inv_colsum_k()
{
    int i = blockIdx.x * 256 + threadIdx.x;
    if (i < BB * NN) {
        float s = g_colsum[i];
        g_colsum[i] = (s > 0.f) ? 1.f / s : 0.f;
    }
}

// ---------------- K3: h' = P @ (H * inv), relu, gate, final mix ----------------
__global__ __launch_bounds__(256, 2) void out_k(const float* __restrict__ x,
                                                const float* __restrict__ gate_w,
                                                const float* __restrict__ gate_b,
                                                float* __restrict__ out)
{
    __shared__ float Ps[16][68];
    __shared__ float Hs[16][132];
    __shared__ float gws[256];
    __shared__ float sred[64][17];
    __shared__ float coef[64];

    int tid = threadIdx.x;
    int tx = tid & 15, ty = tid >> 4;
    int b = blockIdx.y;
    int n0 = blockIdx.x * 64;

    gws[tid] = gate_w[tid];

    const float* Pb = g_P + ((size_t)b * NN + n0) * NN;
    const float* Hb = g_H + (size_t)b * NN * DD;
    const float* cs = g_colsum + b * NN;

    float acc[4][8];
#pragma unroll
    for (int i = 0; i < 4; i++)
#pragma unroll
        for (int j = 0; j < 8; j++) acc[i][j] = 0.f;

    for (int k0 = 0; k0 < NN; k0 += 16) {
        {
            int row = tid >> 2, c4 = tid & 3;
            float4 v = *(const float4*)(Pb + (size_t)row * NN + k0 + c4 * 4);
            Ps[c4 * 4 + 0][row] = v.x; Ps[c4 * 4 + 1][row] = v.y;
            Ps[c4 * 4 + 2][row] = v.z; Ps[c4 * 4 + 3][row] = v.w;
        }
#pragma unroll
        for (int it = 0; it < 2; it++) {
            int f = tid + it * 256; int kk = f >> 5, c4 = f & 31;
            float inv = cs[k0 + kk];
            float4 v = *(const float4*)(Hb + (size_t)(k0 + kk) * DD + c4 * 4);
            Hs[kk][c4 * 4 + 0] = v.x * inv; Hs[kk][c4 * 4 + 1] = v.y * inv;
            Hs[kk][c4 * 4 + 2] = v.z * inv; Hs[kk][c4 * 4 + 3] = v.w * inv;
        }
        __syncthreads();
#pragma unroll
        for (int kk = 0; kk < 16; kk++) {
            float a[4], bv[8];
#pragma unroll
            for (int i = 0; i < 4; i++) a[i] = Ps[kk][ty * 4 + i];
#pragma unroll
            for (int j = 0; j < 8; j++) bv[j] = Hs[kk][tx + 16 * j];
#pragma unroll
            for (int i = 0; i < 4; i++)
#pragma unroll
                for (int j = 0; j < 8; j++) acc[i][j] += a[i] * bv[j];
        }
        __syncthreads();
    }

#pragma unroll
    for (int i = 0; i < 4; i++) {
        int n = n0 + ty * 4 + i;
        float p = 0.f;
#pragma unroll
        for (int j = 0; j < 8; j++) {
            int d = tx + 16 * j;
            float hp = fmaxf(acc[i][j], 0.f);
            acc[i][j] = hp;
            float xv = x[((size_t)b * NN + n) * DD + d];
            p += xv * gws[d] + hp * gws[128 + d];
        }
        sred[ty * 4 + i][tx] = p;
    }
    __syncthreads();
    if (tid < 64) {
        float s = 0.f;
#pragma unroll
        for (int t = 0; t < 16; t++) s += sred[tid][t];
        s += gate_b[0];
        coef[tid] = 1.f / (1.f + __expf(-s));
    }
    __syncthreads();

#pragma unroll
    for (int i = 0; i < 4; i++) {
        int n = n0 + ty * 4 + i;
        float c = coef[ty * 4 + i];
#pragma unroll
        for (int j = 0; j < 8; j++) {
            int d = tx + 16 * j;
            float xv = x[((size_t)b * NN + n) * DD + d];
            out[((size_t)b * NN + n) * DD + d] = c * xv + (1.f - c) * acc[i][j];
        }
    }
}

// ---------------- launch ----------------
extern "C" void kernel_launch(void* const* d_in, const int* in_sizes, int n_in,
                              void* d_out, int out_size)
{
    const float* x      = (const float*)d_in[0];
    const float* adj    = (const float*)d_in[1];
    const float* W_w    = (const float*)d_in[2];
    const float* W_b    = (const float*)d_in[3];
    const float* A_w    = (const float*)d_in[4];
    const float* gate_w = (const float*)d_in[5];
    const float* gate_b = (const float*)d_in[6];
    float* out = (float*)d_out;

    gemm_k<<<BB * NN / 64, 256>>>(x, W_w, W_b, 0);            // g_H = xW + b
    gemm_k<<<BB * NN / 64, 256>>>(nullptr, A_w, nullptr, 1);  // g_G = g_H A
    split_k<<<BB * NN, 128>>>();                              // bf16 hi/lo of [H|G]
    zero_colsum_k<<<BB * NN / 256, 256>>>();
    score_k<<<dim3(NN / 128, NN / 128, BB), 256>>>(adj);      // P, colsum
    inv_colsum_k<<<BB * NN / 256, 256>>>();
    out_k<<<dim3(NN / 64, BB), 256>>>(x, gate_w, gate_b, out);
}

// round 5
// speedup vs baseline: 2.1617x; 1.3584x over previous
#include <cuda_runtime.h>
#include <cuda_bf16.h>
#include <cstdint>

#define BB 8
#define NN 2048
#define DD 128
#define SHIFT 20.0f

// ---------------- scratch (static device globals; no allocation) ----------------
__device__ float g_H[BB * NN * DD];                 // 8 MB
__device__ float g_G[BB * NN * DD];                 // 8 MB
__device__ float g_colsum[BB * NN];
__device__ __nv_bfloat16 g_Shi[(size_t)BB * NN * 256];   // 8 MB  (split [H|G])
__device__ __nv_bfloat16 g_Slo[(size_t)BB * NN * 256];   // 8 MB
__device__ __nv_bfloat16 g_Phi[(size_t)BB * NN * NN];    // 67 MB (split P)
__device__ __nv_bfloat16 g_Plo[(size_t)BB * NN * NN];    // 67 MB
__device__ __nv_bfloat16 g_Thi[(size_t)BB * DD * NN];    // 4 MB  (split H^T * inv)
__device__ __nv_bfloat16 g_Tlo[(size_t)BB * DD * NN];    // 4 MB

// ================= warp MMA helpers (plain PTX, sm_80+) =================
__device__ __forceinline__ uint32_t smem_u32(const void* p) {
    uint32_t a;
    asm("{ .reg .u64 t; cvta.to.shared.u64 t, %1; cvt.u32.u64 %0, t; }" : "=r"(a) : "l"(p));
    return a;
}
__device__ __forceinline__ void ldsm_x4(uint32_t& r0, uint32_t& r1, uint32_t& r2, uint32_t& r3,
                                        uint32_t addr) {
    asm volatile("ldmatrix.sync.aligned.m8n8.x4.shared.b16 {%0,%1,%2,%3}, [%4];"
                 : "=r"(r0), "=r"(r1), "=r"(r2), "=r"(r3) : "r"(addr));
}
__device__ __forceinline__ void mma16816(float* d, const uint32_t* a, uint32_t b0, uint32_t b1) {
    asm volatile(
        "mma.sync.aligned.m16n8k16.row.col.f32.bf16.bf16.f32 "
        "{%0,%1,%2,%3}, {%4,%5,%6,%7}, {%8,%9}, {%0,%1,%2,%3};"
        : "+f"(d[0]), "+f"(d[1]), "+f"(d[2]), "+f"(d[3])
        : "r"(a[0]), "r"(a[1]), "r"(a[2]), "r"(a[3]), "r"(b0), "r"(b1));
}

// ---------------- K1: C[r,c] = X[r,128] @ W[128,128] (+bias) ----------------
__global__ __launch_bounds__(256) void gemm_k(const float* __restrict__ Xin,
                                              const float* __restrict__ W,
                                              const float* __restrict__ bias,
                                              int mode)
{
    __shared__ float Xs[16][68];
    __shared__ float Ws[16][128];
    const float* X = mode ? g_H : Xin;
    float* C = mode ? g_G : g_H;

    int tid = threadIdx.x;
    int tx = tid & 15, ty = tid >> 4;
    int r0 = blockIdx.x * 64;

    float acc[4][8];
#pragma unroll
    for (int i = 0; i < 4; i++)
#pragma unroll
        for (int j = 0; j < 8; j++) acc[i][j] = 0.f;

    for (int k0 = 0; k0 < 128; k0 += 16) {
        {
            int row = tid >> 2, c4 = tid & 3;
            float4 v = *(const float4*)(X + (size_t)(r0 + row) * DD + k0 + c4 * 4);
            Xs[c4 * 4 + 0][row] = v.x; Xs[c4 * 4 + 1][row] = v.y;
            Xs[c4 * 4 + 2][row] = v.z; Xs[c4 * 4 + 3][row] = v.w;
        }
#pragma unroll
        for (int it = 0; it < 2; it++) {
            int f = tid + it * 256; int kk = f >> 5, c4 = f & 31;
            *(float4*)(&Ws[kk][c4 * 4]) = *(const float4*)(W + (size_t)(k0 + kk) * DD + c4 * 4);
        }
        __syncthreads();
#pragma unroll
        for (int kk = 0; kk < 16; kk++) {
            float a[4], bv[8];
#pragma unroll
            for (int i = 0; i < 4; i++) a[i] = Xs[kk][ty * 4 + i];
#pragma unroll
            for (int j = 0; j < 8; j++) bv[j] = Ws[kk][tx + 16 * j];
#pragma unroll
            for (int i = 0; i < 4; i++)
#pragma unroll
                for (int j = 0; j < 8; j++) acc[i][j] += a[i] * bv[j];
        }
        __syncthreads();
    }

    float bj[8];
#pragma unroll
    for (int j = 0; j < 8; j++) bj[j] = bias ? bias[tx + 16 * j] : 0.f;
#pragma unroll
    for (int i = 0; i < 4; i++) {
        int r = r0 + ty * 4 + i;
#pragma unroll
        for (int j = 0; j < 8; j++) {
            int c = tx + 16 * j;
            C[(size_t)r * DD + c] = acc[i][j] + bj[j];
        }
    }
}

// ---------------- split H,G into bf16 hi/lo concatenated rows S=[H|G] ----------------
__global__ __launch_bounds__(128) void split_k()
{
    int row = blockIdx.x;
    int t = threadIdx.x;
    float h = g_H[(size_t)row * DD + t];
    float g = g_G[(size_t)row * DD + t];
    __nv_bfloat16 hh = __float2bfloat16(h);
    __nv_bfloat16 gh = __float2bfloat16(g);
    size_t base = (size_t)row * 256;
    g_Shi[base + t]       = hh;
    g_Slo[base + t]       = __float2bfloat16(h - __bfloat162float(hh));
    g_Shi[base + 128 + t] = gh;
    g_Slo[base + 128 + t] = __float2bfloat16(g - __bfloat162float(gh));
}

// ---------------- zero colsum ----------------
__global__ void zero_colsum_k()
{
    int i = blockIdx.x * 256 + threadIdx.x;
    if (i < BB * NN) g_colsum[i] = 0.f;
}

// ---------------- K2: score kernel via mma.sync bf16 (split fp32) ----------------
#define KC 32
#define LDS_STRIDE 40

__global__ __launch_bounds__(256, 2) void score_k(const float* __restrict__ adj)
{
    __shared__ __nv_bfloat16 sNhi[128 * LDS_STRIDE];
    __shared__ __nv_bfloat16 sNlo[128 * LDS_STRIDE];
    __shared__ __nv_bfloat16 sMhi[128 * LDS_STRIDE];
    __shared__ __nv_bfloat16 sMlo[128 * LDS_STRIDE];

    int tid = threadIdx.x;
    int wid = tid >> 5, lane = tid & 31;
    int gid = lane >> 2, tig = lane & 3;

    int m0 = blockIdx.x * 128;
    int n0 = blockIdx.y * 128;
    int b  = blockIdx.z;

    int mw = (wid >> 2) * 64;
    int nw = (wid & 3) * 32;

    uint32_t aNhi = smem_u32(sNhi), aNlo = smem_u32(sNlo);
    uint32_t aMhi = smem_u32(sMhi), aMlo = smem_u32(sMlo);

    float acc[2][8][4];
#pragma unroll
    for (int i = 0; i < 2; i++)
#pragma unroll
        for (int j = 0; j < 8; j++)
#pragma unroll
            for (int k = 0; k < 4; k++) acc[i][j][k] = 0.f;

    int aRow = lane & 15,                       aKof = (lane >> 4) << 3;
    int bRow = (lane & 7) + ((lane >> 4) << 3), bKof = ((lane >> 3) & 1) << 3;

    for (int c = 0; c < 8; ++c) {
        size_t baseN = ((size_t)b * NN + n0) * 256 + (size_t)(c * KC);
        size_t baseM = ((size_t)b * NN + m0) * 256 + (size_t)(((c + 4) & 7) * KC);
        __syncthreads();
#pragma unroll
        for (int i = 0; i < 2; i++) {
            int f = tid + 256 * i;
            int row = f >> 2, seg = f & 3;
            size_t gn = baseN + (size_t)row * 256 + seg * 8;
            size_t gm = baseM + (size_t)row * 256 + seg * 8;
            uint4 vNh = *(const uint4*)(g_Shi + gn);
            uint4 vNl = *(const uint4*)(g_Slo + gn);
            uint4 vMh = *(const uint4*)(g_Shi + gm);
            uint4 vMl = *(const uint4*)(g_Slo + gm);
            int so = row * LDS_STRIDE + seg * 8;
            *(uint4*)(sNhi + so) = vNh;
            *(uint4*)(sNlo + so) = vNl;
            *(uint4*)(sMhi + so) = vMh;
            *(uint4*)(sMlo + so) = vMl;
        }
        __syncthreads();

#pragma unroll
        for (int pass = 0; pass < 3; pass++) {
            uint32_t At = (pass == 1) ? aNlo : aNhi;
            uint32_t Bt = (pass == 2) ? aMlo : aMhi;
#pragma unroll
            for (int ks = 0; ks < 2; ks++) {
                int k0 = ks * 16;
                uint32_t afr[2][4];
#pragma unroll
                for (int nf = 0; nf < 2; nf++) {
                    uint32_t ad = At + (uint32_t)(((nw + nf * 16 + aRow) * LDS_STRIDE + k0 + aKof) * 2);
                    ldsm_x4(afr[nf][0], afr[nf][1], afr[nf][2], afr[nf][3], ad);
                }
                uint32_t bfr[4][4];
#pragma unroll
                for (int bi = 0; bi < 4; bi++) {
                    uint32_t ad = Bt + (uint32_t)(((mw + bi * 16 + bRow) * LDS_STRIDE + k0 + bKof) * 2);
                    ldsm_x4(bfr[bi][0], bfr[bi][1], bfr[bi][2], bfr[bi][3], ad);
                }
#pragma unroll
                for (int nf = 0; nf < 2; nf++)
#pragma unroll
                    for (int mf = 0; mf < 8; mf++) {
                        uint32_t b0 = bfr[mf >> 1][(mf & 1) ? 2 : 0];
                        uint32_t b1 = bfr[mf >> 1][(mf & 1) ? 3 : 1];
                        mma16816(acc[nf][mf], afr[nf], b0, b1);
                    }
            }
        }
    }

    // epilogue: mask, exp, split-store P (bf16 hi/lo), colsum
    float cs0[8], cs1[8];
#pragma unroll
    for (int mf = 0; mf < 8; mf++) { cs0[mf] = 0.f; cs1[mf] = 0.f; }

#pragma unroll
    for (int nf = 0; nf < 2; nf++) {
#pragma unroll
        for (int half = 0; half < 2; half++) {
            int n = n0 + nw + nf * 16 + gid + half * 8;
            const float2* arow = (const float2*)(adj + ((size_t)b * NN + n) * NN + m0);
            __nv_bfloat162* ph = (__nv_bfloat162*)(g_Phi + ((size_t)b * NN + n) * NN + m0);
            __nv_bfloat162* pl = (__nv_bfloat162*)(g_Plo + ((size_t)b * NN + n) * NN + m0);
#pragma unroll
            for (int mf = 0; mf < 8; mf++) {
                int moff2 = (mw + mf * 8 + tig * 2) >> 1;
                float2 a2 = __ldg(arow + moff2);
                float c0 = acc[nf][mf][half * 2 + 0];
                float c1 = acc[nf][mf][half * 2 + 1];
                float p0 = a2.x * __expf(c0 - SHIFT);
                float p1 = a2.y * __expf(c1 - SHIFT);
                __nv_bfloat16 h0 = __float2bfloat16(p0);
                __nv_bfloat16 h1 = __float2bfloat16(p1);
                ph[moff2] = __nv_bfloat162(h0, h1);
                pl[moff2] = __nv_bfloat162(
                    __float2bfloat16(p0 - __bfloat162float(h0)),
                    __float2bfloat16(p1 - __bfloat162float(h1)));
                cs0[mf] += p0;
                cs1[mf] += p1;
            }
        }
    }
#pragma unroll
    for (int mf = 0; mf < 8; mf++) {
#pragma unroll
        for (int d = 4; d < 32; d <<= 1) {
            cs0[mf] += __shfl_xor_sync(0xFFFFFFFF, cs0[mf], d);
            cs1[mf] += __shfl_xor_sync(0xFFFFFFFF, cs1[mf], d);
        }
        if (lane < 4) {
            int m = m0 + mw + mf * 8 + lane * 2;
            atomicAdd(&g_colsum[b * NN + m],     cs0[mf]);
            atomicAdd(&g_colsum[b * NN + m + 1], cs1[mf]);
        }
    }
}

// ---------------- invert colsum in place ----------------
__global__ void inv_colsum_k()
{
    int i = blockIdx.x * 256 + threadIdx.x;
    if (i < BB * NN) {
        float s = g_colsum[i];
        g_colsum[i] = (s > 0.f) ? 1.f / s : 0.f;
    }
}

// ---------------- transpose + scale + split: T[d][m] = H[m][d]*inv[m] ----------------
__global__ __launch_bounds__(256) void transpose_k()
{
    __shared__ float t[32][33];
    int m0 = blockIdx.x * 32, d0 = blockIdx.y * 32, b = blockIdx.z;
    int tx = threadIdx.x & 31, ty = threadIdx.x >> 5;   // 32 x 8

#pragma unroll
    for (int i = ty; i < 32; i += 8) {
        float inv = g_colsum[b * NN + m0 + i];
        t[i][tx] = g_H[((size_t)b * NN + m0 + i) * DD + d0 + tx] * inv;
    }
    __syncthreads();
#pragma unroll
    for (int i = ty; i < 32; i += 8) {
        float v = t[tx][i];
        __nv_bfloat16 hi = __float2bfloat16(v);
        size_t o = ((size_t)b * DD + d0 + i) * NN + m0 + tx;
        g_Thi[o] = hi;
        g_Tlo[o] = __float2bfloat16(v - __bfloat162float(hi));
    }
}

// ---------------- K3: h' = P @ T^T via mma.sync bf16 (split fp32) ----------------
// D[n][d]: A = P[n][m] (K=2048), B = T[d][m]; passes (Phi,Thi),(Plo,Thi),(Phi,Tlo)
__global__ __launch_bounds__(256, 2) void outmma_k(const float* __restrict__ x,
                                                   const float* __restrict__ gate_w,
                                                   const float* __restrict__ gate_b,
                                                   float* __restrict__ out)
{
    __shared__ __nv_bfloat16 sPhi[128 * LDS_STRIDE];
    __shared__ __nv_bfloat16 sPlo[128 * LDS_STRIDE];
    __shared__ __nv_bfloat16 sThi[128 * LDS_STRIDE];
    __shared__ __nv_bfloat16 sTlo[128 * LDS_STRIDE];
    __shared__ float gws[256];
    __shared__ float sred[2][128];
    __shared__ float coef[128];

    int tid = threadIdx.x;
    int wid = tid >> 5, lane = tid & 31;
    int gid = lane >> 2, tig = lane & 3;

    int n0 = blockIdx.x * 128;
    int b  = blockIdx.y;

    int mw = (wid >> 2) * 64;   // d-warp offset
    int mwid = wid >> 2;
    int nw = (wid & 3) * 32;    // n-warp offset

    gws[tid] = gate_w[tid];

    uint32_t aPhi = smem_u32(sPhi), aPlo = smem_u32(sPlo);
    uint32_t aThi = smem_u32(sThi), aTlo = smem_u32(sTlo);

    float acc[2][8][4];
#pragma unroll
    for (int i = 0; i < 2; i++)
#pragma unroll
        for (int j = 0; j < 8; j++)
#pragma unroll
            for (int k = 0; k < 4; k++) acc[i][j][k] = 0.f;

    int aRow = lane & 15,                       aKof = (lane >> 4) << 3;
    int bRow = (lane & 7) + ((lane >> 4) << 3), bKof = ((lane >> 3) & 1) << 3;

    size_t basePn = ((size_t)b * NN + n0) * NN;   // P rows base
    size_t baseTd = (size_t)b * DD * NN;          // T rows base

    for (int c = 0; c < NN / KC; ++c) {
        int mc = c * KC;
        __syncthreads();
#pragma unroll
        for (int i = 0; i < 2; i++) {
            int f = tid + 256 * i;
            int row = f >> 2, seg = f & 3;
            size_t gp = basePn + (size_t)row * NN + mc + seg * 8;
            size_t gt = baseTd + (size_t)row * NN + mc + seg * 8;
            uint4 vPh = *(const uint4*)(g_Phi + gp);
            uint4 vPl = *(const uint4*)(g_Plo + gp);
            uint4 vTh = *(const uint4*)(g_Thi + gt);
            uint4 vTl = *(const uint4*)(g_Tlo + gt);
            int so = row * LDS_STRIDE + seg * 8;
            *(uint4*)(sPhi + so) = vPh;
            *(uint4*)(sPlo + so) = vPl;
            *(uint4*)(sThi + so) = vTh;
            *(uint4*)(sTlo + so) = vTl;
        }
        __syncthreads();

#pragma unroll
        for (int pass = 0; pass < 3; pass++) {
            uint32_t At = (pass == 1) ? aPlo : aPhi;
            uint32_t Bt = (pass == 2) ? aTlo : aThi;
#pragma unroll
            for (int ks = 0; ks < 2; ks++) {
                int k0 = ks * 16;
                uint32_t afr[2][4];
#pragma unroll
                for (int nf = 0; nf < 2; nf++) {
                    uint32_t ad = At + (uint32_t)(((nw + nf * 16 + aRow) * LDS_STRIDE + k0 + aKof) * 2);
                    ldsm_x4(afr[nf][0], afr[nf][1], afr[nf][2], afr[nf][3], ad);
                }
                uint32_t bfr[4][4];
#pragma unroll
                for (int bi = 0; bi < 4; bi++) {
                    uint32_t ad = Bt + (uint32_t)(((mw + bi * 16 + bRow) * LDS_STRIDE + k0 + bKof) * 2);
                    ldsm_x4(bfr[bi][0], bfr[bi][1], bfr[bi][2], bfr[bi][3], ad);
                }
#pragma unroll
                for (int nf = 0; nf < 2; nf++)
#pragma unroll
                    for (int mf = 0; mf < 8; mf++) {
                        uint32_t b0 = bfr[mf >> 1][(mf & 1) ? 2 : 0];
                        uint32_t b1 = bfr[mf >> 1][(mf & 1) ? 3 : 1];
                        mma16816(acc[nf][mf], afr[nf], b0, b1);
                    }
            }
        }
    }

    // ---------------- epilogue: relu, gate dot, sigmoid, mix ----------------
#pragma unroll
    for (int nf = 0; nf < 2; nf++) {
#pragma unroll
        for (int half = 0; half < 2; half++) {
            int nloc = nw + nf * 16 + gid + half * 8;
            int n = n0 + nloc;
            const float2* xrow = (const float2*)(x + ((size_t)b * NN + n) * DD);
            float partial = 0.f;
#pragma unroll
            for (int mf = 0; mf < 8; mf++) {
                int d = mw + mf * 8 + tig * 2;
                float2 x2 = __ldg(xrow + (d >> 1));
                float hp0 = fmaxf(acc[nf][mf][half * 2 + 0], 0.f);
                float hp1 = fmaxf(acc[nf][mf][half * 2 + 1], 0.f);
                acc[nf][mf][half * 2 + 0] = hp0;
                acc[nf][mf][half * 2 + 1] = hp1;
                partial += x2.x * gws[d] + x2.y * gws[d + 1]
                         + hp0 * gws[128 + d] + hp1 * gws[128 + d + 1];
            }
            partial += __shfl_xor_sync(0xFFFFFFFF, partial, 1);
            partial += __shfl_xor_sync(0xFFFFFFFF, partial, 2);
            if (tig == 0) sred[mwid][nloc] = partial;
        }
    }
    __syncthreads();
    if (tid < 128) {
        float s = sred[0][tid] + sred[1][tid] + gate_b[0];
        coef[tid] = 1.f / (1.f + __expf(-s));
    }
    __syncthreads();

#pragma unroll
    for (int nf = 0; nf < 2; nf++) {
#pragma unroll
        for (int half = 0; half < 2; half++) {
            int nloc = nw + nf * 16 + gid + half * 8;
            int n = n0 + nloc;
            float cf = coef[nloc];
            const float2* xrow = (const float2*)(x + ((size_t)b * NN + n) * DD);
            float2* orow = (float2*)(out + ((size_t)b * NN + n) * DD);
#pragma unroll
            for (int mf = 0; mf < 8; mf++) {
                int d = mw + mf * 8 + tig * 2;
                float2 x2 = __ldg(xrow + (d >> 1));
                float hp0 = acc[nf][mf][half * 2 + 0];
                float hp1 = acc[nf][mf][half * 2 + 1];
                orow[d >> 1] = make_float2(cf * x2.x + (1.f - cf) * hp0,
                                           cf * x2.y + (1.f - cf) * hp1);
            }
        }
    }
}

// ---------------- launch ----------------
extern "C" void kernel_launch(void* const* d_in, const int* in_sizes, int n_in,
                              void* d_out, int out_size)
{
    const float* x      = (const float*)d_in[0];
    const float* adj    = (const float*)d_in[1];
    const float* W_w    = (const float*)d_in[2];
    const float* W_b    = (const float*)d_in[3];
    const float* A_w    = (const float*)d_in[4];
    const float* gate_w = (const float*)d_in[5];
    const float* gate_b = (const float*)d_in[6];
    float* out = (float*)d_out;

    gemm_k<<<BB * NN / 64, 256>>>(x, W_w, W_b, 0);            // g_H = xW + b
    gemm_k<<<BB * NN / 64, 256>>>(nullptr, A_w, nullptr, 1);  // g_G = g_H A
    split_k<<<BB * NN, 128>>>();                              // bf16 hi/lo of [H|G]
    zero_colsum_k<<<BB * NN / 256, 256>>>();
    score_k<<<dim3(NN / 128, NN / 128, BB), 256>>>(adj);      // Phi/Plo, colsum
    inv_colsum_k<<<BB * NN / 256, 256>>>();
    transpose_k<<<dim3(NN / 32, DD / 32, BB), 256>>>();       // Thi/Tlo
    outmma_k<<<dim3(NN / 128, BB), 256>>>(x, gate_w, gate_b, out);
}

// round 6
// speedup vs baseline: 2.5151x; 1.1635x over previous
#include <cuda_runtime.h>
#include <cuda_bf16.h>
#include <cstdint>

#define BB 8
#define NN 2048
#define DD 128
#define SHIFT 20.0f

// ---------------- scratch (static device globals; no allocation) ----------------
__device__ float g_H[BB * NN * DD];                 // 8 MB
__device__ float g_G[BB * NN * DD];                 // 8 MB
__device__ float g_colsum[BB * NN];
__device__ __nv_bfloat16 g_Shi[(size_t)BB * NN * 256];   // 8 MB  (split [H|G])
__device__ __nv_bfloat16 g_Slo[(size_t)BB * NN * 256];   // 8 MB
__device__ __nv_bfloat16 g_Phi[(size_t)BB * NN * NN];    // 67 MB (split P)
__device__ __nv_bfloat16 g_Plo[(size_t)BB * NN * NN];    // 67 MB
__device__ __nv_bfloat16 g_Thi[(size_t)BB * DD * NN];    // 4 MB  (split H^T * inv)
__device__ __nv_bfloat16 g_Tlo[(size_t)BB * DD * NN];    // 4 MB

// ================= warp MMA helpers (plain PTX, sm_80+) =================
__device__ __forceinline__ uint32_t smem_u32(const void* p) {
    uint32_t a;
    asm("{ .reg .u64 t; cvta.to.shared.u64 t, %1; cvt.u32.u64 %0, t; }" : "=r"(a) : "l"(p));
    return a;
}
__device__ __forceinline__ void ldsm_x4(uint32_t& r0, uint32_t& r1, uint32_t& r2, uint32_t& r3,
                                        uint32_t addr) {
    asm volatile("ldmatrix.sync.aligned.m8n8.x4.shared.b16 {%0,%1,%2,%3}, [%4];"
                 : "=r"(r0), "=r"(r1), "=r"(r2), "=r"(r3) : "r"(addr));
}
__device__ __forceinline__ void mma16816(float* d, const uint32_t* a, uint32_t b0, uint32_t b1) {
    asm volatile(
        "mma.sync.aligned.m16n8k16.row.col.f32.bf16.bf16.f32 "
        "{%0,%1,%2,%3}, {%4,%5,%6,%7}, {%8,%9}, {%0,%1,%2,%3};"
        : "+f"(d[0]), "+f"(d[1]), "+f"(d[2]), "+f"(d[3])
        : "r"(a[0]), "r"(a[1]), "r"(a[2]), "r"(a[3]), "r"(b0), "r"(b1));
}

// ---------------- K1: C[r,c] = X[r,128] @ W[128,128] (+bias) ----------------
__global__ __launch_bounds__(256) void gemm_k(const float* __restrict__ Xin,
                                              const float* __restrict__ W,
                                              const float* __restrict__ bias,
                                              int mode)
{
    __shared__ float Xs[16][68];
    __shared__ float Ws[16][128];
    const float* X = mode ? g_H : Xin;
    float* C = mode ? g_G : g_H;

    int tid = threadIdx.x;
    int tx = tid & 15, ty = tid >> 4;
    int r0 = blockIdx.x * 64;

    float acc[4][8];
#pragma unroll
    for (int i = 0; i < 4; i++)
#pragma unroll
        for (int j = 0; j < 8; j++) acc[i][j] = 0.f;

    for (int k0 = 0; k0 < 128; k0 += 16) {
        {
            int row = tid >> 2, c4 = tid & 3;
            float4 v = *(const float4*)(X + (size_t)(r0 + row) * DD + k0 + c4 * 4);
            Xs[c4 * 4 + 0][row] = v.x; Xs[c4 * 4 + 1][row] = v.y;
            Xs[c4 * 4 + 2][row] = v.z; Xs[c4 * 4 + 3][row] = v.w;
        }
#pragma unroll
        for (int it = 0; it < 2; it++) {
            int f = tid + it * 256; int kk = f >> 5, c4 = f & 31;
            *(float4*)(&Ws[kk][c4 * 4]) = *(const float4*)(W + (size_t)(k0 + kk) * DD + c4 * 4);
        }
        __syncthreads();
#pragma unroll
        for (int kk = 0; kk < 16; kk++) {
            float a[4], bv[8];
#pragma unroll
            for (int i = 0; i < 4; i++) a[i] = Xs[kk][ty * 4 + i];
#pragma unroll
            for (int j = 0; j < 8; j++) bv[j] = Ws[kk][tx + 16 * j];
#pragma unroll
            for (int i = 0; i < 4; i++)
#pragma unroll
                for (int j = 0; j < 8; j++) acc[i][j] += a[i] * bv[j];
        }
        __syncthreads();
    }

    float bj[8];
#pragma unroll
    for (int j = 0; j < 8; j++) bj[j] = bias ? bias[tx + 16 * j] : 0.f;
#pragma unroll
    for (int i = 0; i < 4; i++) {
        int r = r0 + ty * 4 + i;
#pragma unroll
        for (int j = 0; j < 8; j++) {
            int c = tx + 16 * j;
            C[(size_t)r * DD + c] = acc[i][j] + bj[j];
        }
    }
}

// ---------------- split H,G into bf16 hi/lo; also zero colsum ----------------
__global__ __launch_bounds__(128) void split_k()
{
    int row = blockIdx.x;
    int t = threadIdx.x;
    if (t == 0) g_colsum[row] = 0.f;
    float h = g_H[(size_t)row * DD + t];
    float g = g_G[(size_t)row * DD + t];
    __nv_bfloat16 hh = __float2bfloat16(h);
    __nv_bfloat16 gh = __float2bfloat16(g);
    size_t base = (size_t)row * 256;
    g_Shi[base + t]       = hh;
    g_Slo[base + t]       = __float2bfloat16(h - __bfloat162float(hh));
    g_Shi[base + 128 + t] = gh;
    g_Slo[base + 128 + t] = __float2bfloat16(g - __bfloat162float(gh));
}

// ---------------- K2: score kernel, symmetric (upper blocks only) ----------------
// e[n,m] = e[m,n]; compute blocks bx(m) >= by(n); off-diag writes both tiles.
#define KC 32
#define LDS_STRIDE 40

__global__ __launch_bounds__(256, 2) void score_k(const float* __restrict__ adj)
{
    __shared__ __nv_bfloat16 sNhi[128 * LDS_STRIDE];
    __shared__ __nv_bfloat16 sNlo[128 * LDS_STRIDE];
    __shared__ __nv_bfloat16 sMhi[128 * LDS_STRIDE];
    __shared__ __nv_bfloat16 sMlo[128 * LDS_STRIDE];

    int bx = blockIdx.x, by = blockIdx.y;
    if (bx < by) return;           // symmetry: only m-block >= n-block

    int tid = threadIdx.x;
    int wid = tid >> 5, lane = tid & 31;
    int gid = lane >> 2, tig = lane & 3;

    int m0 = bx * 128;
    int n0 = by * 128;
    int b  = blockIdx.z;

    int mw = (wid >> 2) * 64;
    int mwid = wid >> 2;
    int nw = (wid & 3) * 32;

    uint32_t aNhi = smem_u32(sNhi), aNlo = smem_u32(sNlo);
    uint32_t aMhi = smem_u32(sMhi), aMlo = smem_u32(sMlo);

    float acc[2][8][4];
#pragma unroll
    for (int i = 0; i < 2; i++)
#pragma unroll
        for (int j = 0; j < 8; j++)
#pragma unroll
            for (int k = 0; k < 4; k++) acc[i][j][k] = 0.f;

    int aRow = lane & 15,                       aKof = (lane >> 4) << 3;
    int bRow = (lane & 7) + ((lane >> 4) << 3), bKof = ((lane >> 3) & 1) << 3;

    for (int c = 0; c < 8; ++c) {
        size_t baseN = ((size_t)b * NN + n0) * 256 + (size_t)(c * KC);
        size_t baseM = ((size_t)b * NN + m0) * 256 + (size_t)(((c + 4) & 7) * KC);
        __syncthreads();
#pragma unroll
        for (int i = 0; i < 2; i++) {
            int f = tid + 256 * i;
            int row = f >> 2, seg = f & 3;
            size_t gn = baseN + (size_t)row * 256 + seg * 8;
            size_t gm = baseM + (size_t)row * 256 + seg * 8;
            uint4 vNh = *(const uint4*)(g_Shi + gn);
            uint4 vNl = *(const uint4*)(g_Slo + gn);
            uint4 vMh = *(const uint4*)(g_Shi + gm);
            uint4 vMl = *(const uint4*)(g_Slo + gm);
            int so = row * LDS_STRIDE + seg * 8;
            *(uint4*)(sNhi + so) = vNh;
            *(uint4*)(sNlo + so) = vNl;
            *(uint4*)(sMhi + so) = vMh;
            *(uint4*)(sMlo + so) = vMl;
        }
        __syncthreads();

#pragma unroll
        for (int pass = 0; pass < 3; pass++) {
            uint32_t At = (pass == 1) ? aNlo : aNhi;
            uint32_t Bt = (pass == 2) ? aMlo : aMhi;
#pragma unroll
            for (int ks = 0; ks < 2; ks++) {
                int k0 = ks * 16;
                uint32_t afr[2][4];
#pragma unroll
                for (int nf = 0; nf < 2; nf++) {
                    uint32_t ad = At + (uint32_t)(((nw + nf * 16 + aRow) * LDS_STRIDE + k0 + aKof) * 2);
                    ldsm_x4(afr[nf][0], afr[nf][1], afr[nf][2], afr[nf][3], ad);
                }
                uint32_t bfr[4][4];
#pragma unroll
                for (int bi = 0; bi < 4; bi++) {
                    uint32_t ad = Bt + (uint32_t)(((mw + bi * 16 + bRow) * LDS_STRIDE + k0 + bKof) * 2);
                    ldsm_x4(bfr[bi][0], bfr[bi][1], bfr[bi][2], bfr[bi][3], ad);
                }
#pragma unroll
                for (int nf = 0; nf < 2; nf++)
#pragma unroll
                    for (int mf = 0; mf < 8; mf++) {
                        uint32_t b0 = bfr[mf >> 1][(mf & 1) ? 2 : 0];
                        uint32_t b1 = bfr[mf >> 1][(mf & 1) ? 3 : 1];
                        mma16816(acc[nf][mf], afr[nf], b0, b1);
                    }
            }
        }
    }

    // ---- exp once, in place ----
#pragma unroll
    for (int i = 0; i < 2; i++)
#pragma unroll
        for (int j = 0; j < 8; j++)
#pragma unroll
            for (int k = 0; k < 4; k++)
                acc[i][j][k] = __expf(acc[i][j][k] - SHIFT);

    // ---- normal tile: P[n,m] = adj[n,m]*ex ; colsum[m] ----
    float cs0[8], cs1[8];
#pragma unroll
    for (int mf = 0; mf < 8; mf++) { cs0[mf] = 0.f; cs1[mf] = 0.f; }

#pragma unroll
    for (int nf = 0; nf < 2; nf++) {
#pragma unroll
        for (int half = 0; half < 2; half++) {
            int n = n0 + nw + nf * 16 + gid + half * 8;
            const float2* arow = (const float2*)(adj + ((size_t)b * NN + n) * NN + m0);
            __nv_bfloat162* ph = (__nv_bfloat162*)(g_Phi + ((size_t)b * NN + n) * NN + m0);
            __nv_bfloat162* pl = (__nv_bfloat162*)(g_Plo + ((size_t)b * NN + n) * NN + m0);
#pragma unroll
            for (int mf = 0; mf < 8; mf++) {
                int moff2 = (mw + mf * 8 + tig * 2) >> 1;
                float2 a2 = __ldg(arow + moff2);
                float p0 = a2.x * acc[nf][mf][half * 2 + 0];
                float p1 = a2.y * acc[nf][mf][half * 2 + 1];
                __nv_bfloat16 h0 = __float2bfloat16(p0);
                __nv_bfloat16 h1 = __float2bfloat16(p1);
                ph[moff2] = __nv_bfloat162(h0, h1);
                pl[moff2] = __nv_bfloat162(
                    __float2bfloat16(p0 - __bfloat162float(h0)),
                    __float2bfloat16(p1 - __bfloat162float(h1)));
                cs0[mf] += p0;
                cs1[mf] += p1;
            }
        }
    }
#pragma unroll
    for (int mf = 0; mf < 8; mf++) {
#pragma unroll
        for (int d = 4; d < 32; d <<= 1) {
            cs0[mf] += __shfl_xor_sync(0xFFFFFFFF, cs0[mf], d);
            cs1[mf] += __shfl_xor_sync(0xFFFFFFFF, cs1[mf], d);
        }
        if (lane < 4) {
            int m = m0 + mw + mf * 8 + lane * 2;
            atomicAdd(&g_colsum[b * NN + m],     cs0[mf]);
            atomicAdd(&g_colsum[b * NN + m + 1], cs1[mf]);
        }
    }

    // ---- mirror tile (off-diagonal only): P[m,n] = adj[m,n]*ex ; colsum[n] ----
    if (bx != by) {
        float rsum[2][2];
        rsum[0][0] = rsum[0][1] = rsum[1][0] = rsum[1][1] = 0.f;
#pragma unroll
        for (int mf = 0; mf < 8; mf++) {
#pragma unroll
            for (int rr = 0; rr < 2; rr++) {
                int m = m0 + mw + mf * 8 + tig * 2 + rr;
                const float* amrow = adj + ((size_t)b * NN + m) * NN + n0;
                __nv_bfloat16* phm = g_Phi + ((size_t)b * NN + m) * NN + n0;
                __nv_bfloat16* plm = g_Plo + ((size_t)b * NN + m) * NN + n0;
#pragma unroll
                for (int nf = 0; nf < 2; nf++) {
#pragma unroll
                    for (int half = 0; half < 2; half++) {
                        int nloc = nw + nf * 16 + half * 8 + gid;
                        float a = __ldg(amrow + nloc);
                        float p = a * acc[nf][mf][half * 2 + rr];
                        __nv_bfloat16 hp = __float2bfloat16(p);
                        phm[nloc] = hp;
                        plm[nloc] = __float2bfloat16(p - __bfloat162float(hp));
                        rsum[nf][half] += p;
                    }
                }
            }
        }
        // reduce over tig (m within warp), then across 2 m-warps via smem
#pragma unroll
        for (int nf = 0; nf < 2; nf++)
#pragma unroll
            for (int half = 0; half < 2; half++) {
                float v = rsum[nf][half];
                v += __shfl_xor_sync(0xFFFFFFFF, v, 1);
                v += __shfl_xor_sync(0xFFFFFFFF, v, 2);
                rsum[nf][half] = v;
            }
        __syncthreads();                       // smem reuse safe (MMA done)
        float* red = (float*)sNhi;             // [2][128]
        if (tig == 0) {
#pragma unroll
            for (int nf = 0; nf < 2; nf++)
#pragma unroll
                for (int half = 0; half < 2; half++) {
                    int nloc = nw + nf * 16 + half * 8 + gid;
                    red[mwid * 128 + nloc] = rsum[nf][half];
                }
        }
        __syncthreads();
        if (tid < 128)
            atomicAdd(&g_colsum[b * NN + n0 + tid], red[tid] + red[128 + tid]);
    }
}

// ---------------- invert colsum in place ----------------
__global__ void inv_colsum_k()
{
    int i = blockIdx.x * 256 + threadIdx.x;
    if (i < BB * NN) {
        float s = g_colsum[i];
        g_colsum[i] = (s > 0.f) ? 1.f / s : 0.f;
    }
}

// ---------------- transpose + scale + split: T[d][m] = H[m][d]*inv[m] ----------------
__global__ __launch_bounds__(256) void transpose_k()
{
    __shared__ float t[32][33];
    int m0 = blockIdx.x * 32, d0 = blockIdx.y * 32, b = blockIdx.z;
    int tx = threadIdx.x & 31, ty = threadIdx.x >> 5;   // 32 x 8

#pragma unroll
    for (int i = ty; i < 32; i += 8) {
        float inv = g_colsum[b * NN + m0 + i];
        t[i][tx] = g_H[((size_t)b * NN + m0 + i) * DD + d0 + tx] * inv;
    }
    __syncthreads();
#pragma unroll
    for (int i = ty; i < 32; i += 8) {
        float v = t[tx][i];
        __nv_bfloat16 hi = __float2bfloat16(v);
        size_t o = ((size_t)b * DD + d0 + i) * NN + m0 + tx;
        g_Thi[o] = hi;
        g_Tlo[o] = __float2bfloat16(v - __bfloat162float(hi));
    }
}

// ---------------- K3: h' = P @ T^T via mma.sync bf16 (split fp32) ----------------
__global__ __launch_bounds__(256, 2) void outmma_k(const float* __restrict__ x,
                                                   const float* __restrict__ gate_w,
                                                   const float* __restrict__ gate_b,
                                                   float* __restrict__ out)
{
    __shared__ __nv_bfloat16 sPhi[128 * LDS_STRIDE];
    __shared__ __nv_bfloat16 sPlo[128 * LDS_STRIDE];
    __shared__ __nv_bfloat16 sThi[128 * LDS_STRIDE];
    __shared__ __nv_bfloat16 sTlo[128 * LDS_STRIDE];
    __shared__ float gws[256];
    __shared__ float sred[2][128];
    __shared__ float coef[128];

    int tid = threadIdx.x;
    int wid = tid >> 5, lane = tid & 31;
    int gid = lane >> 2, tig = lane & 3;

    int n0 = blockIdx.x * 128;
    int b  = blockIdx.y;

    int mw = (wid >> 2) * 64;
    int mwid = wid >> 2;
    int nw = (wid & 3) * 32;

    gws[tid] = gate_w[tid];

    uint32_t aPhi = smem_u32(sPhi), aPlo = smem_u32(sPlo);
    uint32_t aThi = smem_u32(sThi), aTlo = smem_u32(sTlo);

    float acc[2][8][4];
#pragma unroll
    for (int i = 0; i < 2; i++)
#pragma unroll
        for (int j = 0; j < 8; j++)
#pragma unroll
            for (int k = 0; k < 4; k++) acc[i][j][k] = 0.f;

    int aRow = lane & 15,                       aKof = (lane >> 4) << 3;
    int bRow = (lane & 7) + ((lane >> 4) << 3), bKof = ((lane >> 3) & 1) << 3;

    size_t basePn = ((size_t)b * NN + n0) * NN;
    size_t baseTd = (size_t)b * DD * NN;

    for (int c = 0; c < NN / KC; ++c) {
        int mc = c * KC;
        __syncthreads();
#pragma unroll
        for (int i = 0; i < 2; i++) {
            int f = tid + 256 * i;
            int row = f >> 2, seg = f & 3;
            size_t gp = basePn + (size_t)row * NN + mc + seg * 8;
            size_t gt = baseTd + (size_t)row * NN + mc + seg * 8;
            uint4 vPh = *(const uint4*)(g_Phi + gp);
            uint4 vPl = *(const uint4*)(g_Plo + gp);
            uint4 vTh = *(const uint4*)(g_Thi + gt);
            uint4 vTl = *(const uint4*)(g_Tlo + gt);
            int so = row * LDS_STRIDE + seg * 8;
            *(uint4*)(sPhi + so) = vPh;
            *(uint4*)(sPlo + so) = vPl;
            *(uint4*)(sThi + so) = vTh;
            *(uint4*)(sTlo + so) = vTl;
        }
        __syncthreads();

#pragma unroll
        for (int pass = 0; pass < 3; pass++) {
            uint32_t At = (pass == 1) ? aPlo : aPhi;
            uint32_t Bt = (pass == 2) ? aTlo : aThi;
#pragma unroll
            for (int ks = 0; ks < 2; ks++) {
                int k0 = ks * 16;
                uint32_t afr[2][4];
#pragma unroll
                for (int nf = 0; nf < 2; nf++) {
                    uint32_t ad = At + (uint32_t)(((nw + nf * 16 + aRow) * LDS_STRIDE + k0 + aKof) * 2);
                    ldsm_x4(afr[nf][0], afr[nf][1], afr[nf][2], afr[nf][3], ad);
                }
                uint32_t bfr[4][4];
#pragma unroll
                for (int bi = 0; bi < 4; bi++) {
                    uint32_t ad = Bt + (uint32_t)(((mw + bi * 16 + bRow) * LDS_STRIDE + k0 + bKof) * 2);
                    ldsm_x4(bfr[bi][0], bfr[bi][1], bfr[bi][2], bfr[bi][3], ad);
                }
#pragma unroll
                for (int nf = 0; nf < 2; nf++)
#pragma unroll
                    for (int mf = 0; mf < 8; mf++) {
                        uint32_t b0 = bfr[mf >> 1][(mf & 1) ? 2 : 0];
                        uint32_t b1 = bfr[mf >> 1][(mf & 1) ? 3 : 1];
                        mma16816(acc[nf][mf], afr[nf], b0, b1);
                    }
            }
        }
    }

    // ---------------- epilogue: relu, gate dot, sigmoid, mix ----------------
#pragma unroll
    for (int nf = 0; nf < 2; nf++) {
#pragma unroll
        for (int half = 0; half < 2; half++) {
            int nloc = nw + nf * 16 + gid + half * 8;
            int n = n0 + nloc;
            const float2* xrow = (const float2*)(x + ((size_t)b * NN + n) * DD);
            float partial = 0.f;
#pragma unroll
            for (int mf = 0; mf < 8; mf++) {
                int d = mw + mf * 8 + tig * 2;
                float2 x2 = __ldg(xrow + (d >> 1));
                float hp0 = fmaxf(acc[nf][mf][half * 2 + 0], 0.f);
                float hp1 = fmaxf(acc[nf][mf][half * 2 + 1], 0.f);
                acc[nf][mf][half * 2 + 0] = hp0;
                acc[nf][mf][half * 2 + 1] = hp1;
                partial += x2.x * gws[d] + x2.y * gws[d + 1]
                         + hp0 * gws[128 + d] + hp1 * gws[128 + d + 1];
            }
            partial += __shfl_xor_sync(0xFFFFFFFF, partial, 1);
            partial += __shfl_xor_sync(0xFFFFFFFF, partial, 2);
            if (tig == 0) sred[mwid][nloc] = partial;
        }
    }
    __syncthreads();
    if (tid < 128) {
        float s = sred[0][tid] + sred[1][tid] + gate_b[0];
        coef[tid] = 1.f / (1.f + __expf(-s));
    }
    __syncthreads();

#pragma unroll
    for (int nf = 0; nf < 2; nf++) {
#pragma unroll
        for (int half = 0; half < 2; half++) {
            int nloc = nw + nf * 16 + gid + half * 8;
            int n = n0 + nloc;
            float cf = coef[nloc];
            const float2* xrow = (const float2*)(x + ((size_t)b * NN + n) * DD);
            float2* orow = (float2*)(out + ((size_t)b * NN + n) * DD);
#pragma unroll
            for (int mf = 0; mf < 8; mf++) {
                int d = mw + mf * 8 + tig * 2;
                float2 x2 = __ldg(xrow + (d >> 1));
                float hp0 = acc[nf][mf][half * 2 + 0];
                float hp1 = acc[nf][mf][half * 2 + 1];
                orow[d >> 1] = make_float2(cf * x2.x + (1.f - cf) * hp0,
                                           cf * x2.y + (1.f - cf) * hp1);
            }
        }
    }
}

// ---------------- launch ----------------
extern "C" void kernel_launch(void* const* d_in, const int* in_sizes, int n_in,
                              void* d_out, int out_size)
{
    const float* x      = (const float*)d_in[0];
    const float* adj    = (const float*)d_in[1];
    const float* W_w    = (const float*)d_in[2];
    const float* W_b    = (const float*)d_in[3];
    const float* A_w    = (const float*)d_in[4];
    const float* gate_w = (const float*)d_in[5];
    const float* gate_b = (const float*)d_in[6];
    float* out = (float*)d_out;

    gemm_k<<<BB * NN / 64, 256>>>(x, W_w, W_b, 0);            // g_H = xW + b
    gemm_k<<<BB * NN / 64, 256>>>(nullptr, A_w, nullptr, 1);  // g_G = g_H A
    split_k<<<BB * NN, 128>>>();                              // bf16 hi/lo + zero colsum
    score_k<<<dim3(NN / 128, NN / 128, BB), 256>>>(adj);      // Phi/Plo, colsum (sym)
    inv_colsum_k<<<BB * NN / 256, 256>>>();
    transpose_k<<<dim3(NN / 32, DD / 32, BB), 256>>>();       // Thi/Tlo
    outmma_k<<<dim3(NN / 128, BB), 256>>>(x, gate_w, gate_b, out);
}